// round 1
// baseline (speedup 1.0000x reference)
#include <cuda_runtime.h>
#include <cstdint>

#define NNODES 50000
#define EDGES 800000
#define FIN 256
#define HID 256
#define NJ 3
#define NCAT 1024          // H*(NJ+1)
#define NCLS 40
#define BN_EPS 1e-5f

// ---------------- scratch (static device globals; no allocation) ------------
__device__ float g_T1[(size_t)NNODES * NCAT];     // x @ Wcat (and later T2 in slice 3)
__device__ float g_AGG[(size_t)NNODES * NCAT];    // aggregation results -> becomes FINAL
__device__ float g_AGG2[(size_t)NNODES * HID];    // second extra-layer aggregation
__device__ float g_deg[4 * NNODES];
__device__ float g_dinv[4 * NNODES];
__device__ float g_invdeg[4 * NNODES];
__device__ float g_Wcat[FIN * NCAT];
__device__ float g_logits[(size_t)NNODES * NCLS];
__device__ float g_mask[4];

// ---------------- tiny kernels ---------------------------------------------
__global__ void mask_kernel(const float* __restrict__ att) {
    if (threadIdx.x == 0) {
        float m = att[0];
        for (int i = 1; i < 4; i++) m = fmaxf(m, att[i]);
        float s = 0.f, e[4];
        for (int i = 0; i < 4; i++) { e[i] = expf(att[i] - m); s += e[i]; }
        for (int i = 0; i < 4; i++) g_mask[i] = e[i] / s;
    }
}

__global__ void fill_kernel(float* p, float v, int n) {
    int i = blockIdx.x * blockDim.x + threadIdx.x;
    if (i < n) p[i] = v;
}

__global__ void zero4_kernel(float4* p, int n4) {
    int i = blockIdx.x * blockDim.x + threadIdx.x;
    if (i < n4) p[i] = make_float4(0.f, 0.f, 0.f, 0.f);
}

__global__ void count_deg_kernel(const int* __restrict__ adj) {
    int i = blockIdx.x * blockDim.x + threadIdx.x;     // over 4*E
    if (i >= 4 * EDGES) return;
    int j = i / EDGES;
    int e = i - j * EDGES;
    int dst = adj[(size_t)j * 2 * EDGES + EDGES + e];
    atomicAdd(&g_deg[j * NNODES + dst], 1.0f);
}

__global__ void finalize_deg_kernel() {
    int i = blockIdx.x * blockDim.x + threadIdx.x;
    if (i >= 4 * NNODES) return;
    float d = g_deg[i];
    g_dinv[i]   = rsqrtf(d);
    g_invdeg[i] = 1.0f / d;
}

__global__ void pack_wcat_kernel(const float* __restrict__ W_convs,
                                 const float* __restrict__ W_extra) {
    int i = blockIdx.x * blockDim.x + threadIdx.x;     // over FIN*NCAT
    if (i >= FIN * NCAT) return;
    int k = i / NCAT;
    int c = i - k * NCAT;
    float v;
    if (c < 3 * HID) {
        int br = c / HID, h = c - br * HID;
        v = W_convs[(size_t)br * FIN * HID + (size_t)k * HID + h];
    } else {
        v = W_extra[(size_t)k * HID + (c - 3 * HID)];
    }
    g_Wcat[i] = v;
}

// ---------------- GEMM: C[M,Nc] = A[M,K](lda) * B[K,Nc](ldb) ----------------
#define BM 128
#define BN 64
#define BK 16
#define TM 8
#define TN 4
__global__ __launch_bounds__(256) void gemm_kernel(
    const float* __restrict__ A, int lda,
    const float* __restrict__ B, int ldb,
    float* __restrict__ C, int ldc,
    int M, int K) {
    __shared__ float As[BK][BM];
    __shared__ float Bs[BK][BN];
    int tid = threadIdx.x;
    int bm = blockIdx.y * BM;
    int bn = blockIdx.x * BN;
    int tx = tid & 15;       // n dir
    int ty = tid >> 4;       // m dir
    float acc[TM][TN];
#pragma unroll
    for (int i = 0; i < TM; i++)
#pragma unroll
        for (int j = 0; j < TN; j++) acc[i][j] = 0.f;

    for (int k0 = 0; k0 < K; k0 += BK) {
        // A tile: 128 rows x 16 cols = 512 float4, 2 per thread; store transposed
#pragma unroll
        for (int t = 0; t < 2; t++) {
            int q = tid + t * 256;
            int row = q >> 2;
            int col = (q & 3) * 4;
            float4 v = make_float4(0.f, 0.f, 0.f, 0.f);
            int gm = bm + row;
            if (gm < M) v = *(const float4*)(A + (size_t)gm * lda + k0 + col);
            As[col + 0][row] = v.x;
            As[col + 1][row] = v.y;
            As[col + 2][row] = v.z;
            As[col + 3][row] = v.w;
        }
        // B tile: 16 x 64 = 256 float4, 1 per thread
        {
            int row = tid >> 4;
            int col = (tid & 15) * 4;
            float4 v = *(const float4*)(B + (size_t)(k0 + row) * ldb + bn + col);
            Bs[row][col + 0] = v.x;
            Bs[row][col + 1] = v.y;
            Bs[row][col + 2] = v.z;
            Bs[row][col + 3] = v.w;
        }
        __syncthreads();
#pragma unroll
        for (int kk = 0; kk < BK; kk++) {
            float ra[TM], rb[TN];
#pragma unroll
            for (int i = 0; i < TM; i++) ra[i] = As[kk][ty * TM + i];
#pragma unroll
            for (int j = 0; j < TN; j++) rb[j] = Bs[kk][tx * TN + j];
#pragma unroll
            for (int i = 0; i < TM; i++)
#pragma unroll
                for (int j = 0; j < TN; j++) acc[i][j] += ra[i] * rb[j];
        }
        __syncthreads();
    }
#pragma unroll
    for (int i = 0; i < TM; i++) {
        int gm = bm + ty * TM + i;
        if (gm < M) {
            float* cp = C + (size_t)gm * ldc + bn + tx * TN;
#pragma unroll
            for (int j = 0; j < TN; j++) cp[j] = acc[i][j];
        }
    }
}

// ---------------- edge aggregation: warp per edge ---------------------------
// Adst[dst, :HID] += dinv[src]*dinv[dst] * Hsrc[src, :HID]
__global__ __launch_bounds__(256) void agg_kernel(
    const int* __restrict__ srcs, const int* __restrict__ dsts,
    const float* __restrict__ dinv,
    const float* __restrict__ Hsrc, int ldH,
    float* __restrict__ Adst, int ldA) {
    int warp = (blockIdx.x * blockDim.x + threadIdx.x) >> 5;
    int lane = threadIdx.x & 31;
    if (warp >= EDGES) return;
    int s = srcs[warp];
    int d = dsts[warp];
    float w = dinv[s] * dinv[d];
    const float4* hp = (const float4*)(Hsrc + (size_t)s * ldH) + lane * 2;
    float*        ap = Adst + (size_t)d * ldA + lane * 8;
    float4 v0 = hp[0];
    float4 v1 = hp[1];
    atomicAdd(ap + 0, w * v0.x);
    atomicAdd(ap + 1, w * v0.y);
    atomicAdd(ap + 2, w * v0.z);
    atomicAdd(ap + 3, w * v0.w);
    atomicAdd(ap + 4, w * v1.x);
    atomicAdd(ap + 5, w * v1.y);
    atomicAdd(ap + 6, w * v1.z);
    atomicAdd(ap + 7, w * v1.w);
}

// ---------------- epilogues -------------------------------------------------
// slices 0..2: FINAL = relu(AGG + T1*invdeg + b_conv) * mask[s]   (in place on AGG)
__global__ void epi_conv_kernel(const float* __restrict__ bias, int s, int adj_idx) {
    int idx = blockIdx.x * blockDim.x + threadIdx.x;   // over N * 64 float4
    if (idx >= NNODES * 64) return;
    int n = idx >> 6;
    int h4 = (idx & 63) * 4;
    size_t off = (size_t)n * NCAT + s * HID + h4;
    float id = g_invdeg[adj_idx * NNODES + n];
    float mk = g_mask[s];
    float4 a = *(float4*)(g_AGG + off);
    float4 t = *(const float4*)(g_T1 + off);
    float4 b = *(const float4*)(bias + h4);
    a.x = fmaxf(a.x + t.x * id + b.x, 0.f) * mk;
    a.y = fmaxf(a.y + t.y * id + b.y, 0.f) * mk;
    a.z = fmaxf(a.z + t.z * id + b.z, 0.f) * mk;
    a.w = fmaxf(a.w + t.w * id + b.w, 0.f) * mk;
    *(float4*)(g_AGG + off) = a;
}

// slice 3 layer 1: e1 = relu(bn1(AGG + T1*invdeg0 + b_extra))   (in place on AGG)
__global__ void epi_extra1_kernel(const float* __restrict__ bias,
                                  const float* __restrict__ gam,
                                  const float* __restrict__ bet,
                                  const float* __restrict__ mean,
                                  const float* __restrict__ var) {
    int idx = blockIdx.x * blockDim.x + threadIdx.x;
    if (idx >= NNODES * 64) return;
    int n = idx >> 6;
    int h4 = (idx & 63) * 4;
    size_t off = (size_t)n * NCAT + 3 * HID + h4;
    float id = g_invdeg[0 * NNODES + n];
    float4 a = *(float4*)(g_AGG + off);
    float4 t = *(const float4*)(g_T1 + off);
    float4 b = *(const float4*)(bias + h4);
    float4 G = *(const float4*)(gam + h4);
    float4 Bt = *(const float4*)(bet + h4);
    float4 Mn = *(const float4*)(mean + h4);
    float4 Vr = *(const float4*)(var + h4);
    a.x = fmaxf((a.x + t.x * id + b.x - Mn.x) * rsqrtf(Vr.x + BN_EPS) * G.x + Bt.x, 0.f);
    a.y = fmaxf((a.y + t.y * id + b.y - Mn.y) * rsqrtf(Vr.y + BN_EPS) * G.y + Bt.y, 0.f);
    a.z = fmaxf((a.z + t.z * id + b.z - Mn.z) * rsqrtf(Vr.z + BN_EPS) * G.z + Bt.z, 0.f);
    a.w = fmaxf((a.w + t.w * id + b.w - Mn.w) * rsqrtf(Vr.w + BN_EPS) * G.w + Bt.w, 0.f);
    *(float4*)(g_AGG + off) = a;
}

// slice 3 layer 2: FINAL3 = relu(bn2(AGG2 + T2*invdeg0 + b_extra2)) * mask[3]
__global__ void epi_extra2_kernel(const float* __restrict__ bias,
                                  const float* __restrict__ gam,
                                  const float* __restrict__ bet,
                                  const float* __restrict__ mean,
                                  const float* __restrict__ var) {
    int idx = blockIdx.x * blockDim.x + threadIdx.x;
    if (idx >= NNODES * 64) return;
    int n = idx >> 6;
    int h4 = (idx & 63) * 4;
    float id = g_invdeg[0 * NNODES + n];
    float mk = g_mask[3];
    float4 a = *(const float4*)(g_AGG2 + (size_t)n * HID + h4);
    float4 t = *(const float4*)(g_T1 + (size_t)n * NCAT + 3 * HID + h4);
    float4 b = *(const float4*)(bias + h4);
    float4 G = *(const float4*)(gam + h4);
    float4 Bt = *(const float4*)(bet + h4);
    float4 Mn = *(const float4*)(mean + h4);
    float4 Vr = *(const float4*)(var + h4);
    a.x = fmaxf((a.x + t.x * id + b.x - Mn.x) * rsqrtf(Vr.x + BN_EPS) * G.x + Bt.x, 0.f) * mk;
    a.y = fmaxf((a.y + t.y * id + b.y - Mn.y) * rsqrtf(Vr.y + BN_EPS) * G.y + Bt.y, 0.f) * mk;
    a.z = fmaxf((a.z + t.z * id + b.z - Mn.z) * rsqrtf(Vr.z + BN_EPS) * G.z + Bt.z, 0.f) * mk;
    a.w = fmaxf((a.w + t.w * id + b.w - Mn.w) * rsqrtf(Vr.w + BN_EPS) * G.w + Bt.w, 0.f) * mk;
    *(float4*)(g_AGG + (size_t)n * NCAT + 3 * HID + h4) = a;
}

// ---------------- classifier: logits = FINAL[N,1024] @ W_cls[1024,40] + b ---
__global__ __launch_bounds__(320) void cls_kernel(const float* __restrict__ W_cls,
                                                  const float* __restrict__ b_cls) {
    __shared__ float sh[8 * NCAT];                   // 32 KB: 8 node rows
    int c = threadIdx.x;                             // 0..39  (class)
    int r = threadIdx.y;                             // 0..7   (node in block)
    int tid = r * NCLS + c;
    int n0 = blockIdx.x * 8;
    for (int i = tid; i < 8 * NCAT; i += 320) {
        int rr = i >> 10;
        int kk = i & (NCAT - 1);
        int n = n0 + rr;
        sh[i] = (n < NNODES) ? g_AGG[(size_t)n * NCAT + kk] : 0.f;
    }
    __syncthreads();
    int n = n0 + r;
    if (n >= NNODES) return;
    float acc = b_cls[c];
    const float* row = sh + r * NCAT;
#pragma unroll 8
    for (int k = 0; k < NCAT; k++) acc += row[k] * W_cls[k * NCLS + c];
    g_logits[(size_t)n * NCLS + c] = acc;
}

// ---------------- log_softmax (warp per node) + tail fill -------------------
__global__ void lsm_kernel(float* __restrict__ out) {
    int warp = (blockIdx.x * blockDim.x + threadIdx.x) >> 5;
    int lane = threadIdx.x & 31;
    if (warp >= NNODES) return;
    const float* lg = g_logits + (size_t)warp * NCLS;
    float v0 = (lane < NCLS) ? lg[lane] : -1e30f;
    float v1 = (lane + 32 < NCLS) ? lg[lane + 32] : -1e30f;
    float m = fmaxf(v0, v1);
#pragma unroll
    for (int o = 16; o > 0; o >>= 1) m = fmaxf(m, __shfl_xor_sync(0xffffffffu, m, o));
    float s = ((lane < NCLS) ? expf(v0 - m) : 0.f) + ((lane + 32 < NCLS) ? expf(v1 - m) : 0.f);
#pragma unroll
    for (int o = 16; o > 0; o >>= 1) s += __shfl_xor_sync(0xffffffffu, s, o);
    float L = m + logf(s);
    float* op = out + (size_t)warp * NCLS;
    if (lane < NCLS) op[lane] = v0 - L;
    if (lane + 32 < NCLS) op[lane + 32] = v1 - L;
}

__global__ void tail_kernel(float* out, int start, int total) {
    int i = start + blockIdx.x * blockDim.x + threadIdx.x;
    if (i < total) out[i] = 0.f;
}

// ---------------- launch ----------------------------------------------------
extern "C" void kernel_launch(void* const* d_in, const int* in_sizes, int n_in,
                              void* d_out, int out_size) {
    const float* x        = (const float*)d_in[0];
    const int*   adj      = (const int*)d_in[1];
    const float* W_convs  = (const float*)d_in[2];
    const float* b_convs  = (const float*)d_in[3];
    const float* W_extra  = (const float*)d_in[4];
    const float* b_extra  = (const float*)d_in[5];
    const float* bn1g     = (const float*)d_in[6];
    const float* bn1b     = (const float*)d_in[7];
    const float* bn1m     = (const float*)d_in[8];
    const float* bn1v     = (const float*)d_in[9];
    const float* W_extra2 = (const float*)d_in[10];
    const float* b_extra2 = (const float*)d_in[11];
    const float* bn2g     = (const float*)d_in[12];
    const float* bn2b     = (const float*)d_in[13];
    const float* bn2m     = (const float*)d_in[14];
    const float* bn2v     = (const float*)d_in[15];
    const float* att      = (const float*)d_in[16];
    const float* W_cls    = (const float*)d_in[17];
    const float* b_cls    = (const float*)d_in[18];
    float* out = (float*)d_out;

    float *p_T1, *p_AGG, *p_AGG2, *p_deg, *p_dinv, *p_Wcat;
    cudaGetSymbolAddress((void**)&p_T1,   g_T1);
    cudaGetSymbolAddress((void**)&p_AGG,  g_AGG);
    cudaGetSymbolAddress((void**)&p_AGG2, g_AGG2);
    cudaGetSymbolAddress((void**)&p_deg,  g_deg);
    cudaGetSymbolAddress((void**)&p_dinv, g_dinv);
    cudaGetSymbolAddress((void**)&p_Wcat, g_Wcat);

    // prep
    mask_kernel<<<1, 32>>>(att);
    fill_kernel<<<(4 * NNODES + 255) / 256, 256>>>(p_deg, 1.0f, 4 * NNODES);  // +1 self loop
    count_deg_kernel<<<(4 * EDGES + 255) / 256, 256>>>(adj);
    finalize_deg_kernel<<<(4 * NNODES + 255) / 256, 256>>>();
    pack_wcat_kernel<<<(FIN * NCAT + 255) / 256, 256>>>(W_convs, W_extra);
    zero4_kernel<<<(NNODES * NCAT / 4 + 255) / 256, 256>>>((float4*)p_AGG, NNODES * NCAT / 4);
    zero4_kernel<<<(NNODES * HID / 4 + 255) / 256, 256>>>((float4*)p_AGG2, NNODES * HID / 4);

    // GEMM1: T1 = x @ Wcat   [50000,1024]
    {
        dim3 grid(NCAT / BN, (NNODES + BM - 1) / BM);
        gemm_kernel<<<grid, 256>>>(x, FIN, p_Wcat, NCAT, p_T1, NCAT, NNODES, FIN);
    }

    // per-slice aggregation + epilogue (serialized for L2 residency)
    int agg_blocks = (EDGES * 32 + 255) / 256;
    int epi_blocks = (NNODES * 64 + 255) / 256;
    for (int s = 0; s < 3; s++) {
        int a = s + 1;                      // conv slice s uses adj[s+1]
        const int* srcs = adj + (size_t)a * 2 * EDGES;
        const int* dsts = srcs + EDGES;
        agg_kernel<<<agg_blocks, 256>>>(srcs, dsts, p_dinv + a * NNODES,
                                        p_T1 + s * HID, NCAT,
                                        p_AGG + s * HID, NCAT);
        epi_conv_kernel<<<epi_blocks, 256>>>(b_convs + s * HID, s, a);
    }
    // extra branch layer 1 on adj[0]
    {
        const int* srcs = adj;              // adj[0]
        const int* dsts = adj + EDGES;
        agg_kernel<<<agg_blocks, 256>>>(srcs, dsts, p_dinv,
                                        p_T1 + 3 * HID, NCAT,
                                        p_AGG + 3 * HID, NCAT);
        epi_extra1_kernel<<<epi_blocks, 256>>>(b_extra, bn1g, bn1b, bn1m, bn1v);
    }
    // GEMM2: T2 (stored into T1 slice 3) = e1 @ W_extra2
    {
        dim3 grid(HID / BN, (NNODES + BM - 1) / BM);
        gemm_kernel<<<grid, 256>>>(p_AGG + 3 * HID, NCAT, W_extra2, HID,
                                   p_T1 + 3 * HID, NCAT, NNODES, HID);
    }
    // extra layer 2 aggregation on adj[0] into AGG2
    {
        const int* srcs = adj;
        const int* dsts = adj + EDGES;
        agg_kernel<<<agg_blocks, 256>>>(srcs, dsts, p_dinv,
                                        p_T1 + 3 * HID, NCAT,
                                        p_AGG2, HID);
        epi_extra2_kernel<<<epi_blocks, 256>>>(b_extra2, bn2g, bn2b, bn2m, bn2v);
    }

    // classifier + log_softmax
    {
        dim3 blk(NCLS, 8);
        cls_kernel<<<(NNODES + 7) / 8, blk>>>(W_cls, b_cls);
        lsm_kernel<<<(NNODES + 7) / 8, 256>>>(out);
        int tail = out_size - NNODES * NCLS;
        if (tail > 0)
            tail_kernel<<<(tail + 255) / 256, 256>>>(out, NNODES * NCLS, out_size);
    }
}

// round 3
// speedup vs baseline: 4.2156x; 4.2156x over previous
#include <cuda_runtime.h>
#include <cstdint>

#define NNODES 50000
#define EDGES 800000
#define FIN 256
#define HID 256
#define NCAT 1024
#define NCLS 40
#define BN_EPS 1e-5f
#define NTOT (4 * NNODES)
#define ETOT (4 * EDGES)

// ---------------- scratch (static device globals) ---------------------------
__device__ float g_T1[(size_t)NNODES * NCAT];     // x @ Wcat; slice3 later holds T2
__device__ float g_AGG[(size_t)NNODES * NCAT];    // aggregation output -> FINAL
__device__ int   g_cnt[NTOT];
__device__ float g_dinv[NTOT];
__device__ float g_invdeg[NTOT];
__device__ int   g_start[NTOT + 1];
__device__ int   g_cursor[NTOT];
__device__ int   g_bsum[1024];
__device__ int   g_esrc[ETOT];
__device__ float g_ew[ETOT];
__device__ float g_Wcat[FIN * NCAT];
__device__ float g_Wt[NCLS * NCAT];
__device__ float g_mask[4];
__device__ float g_bn1s[HID], g_bn1t[HID], g_bn2s[HID], g_bn2t[HID];

// ---------------- tiny prep kernels -----------------------------------------
__global__ void mask_kernel(const float* __restrict__ att) {
    if (threadIdx.x == 0) {
        float m = att[0];
        for (int i = 1; i < 4; i++) m = fmaxf(m, att[i]);
        float s = 0.f, e[4];
        for (int i = 0; i < 4; i++) { e[i] = expf(att[i] - m); s += e[i]; }
        for (int i = 0; i < 4; i++) g_mask[i] = e[i] / s;
    }
}

__global__ void bnfold_kernel(const float* g1, const float* b1, const float* m1, const float* v1,
                              const float* g2, const float* b2, const float* m2, const float* v2) {
    int i = blockIdx.x * blockDim.x + threadIdx.x;
    if (i >= HID) return;
    float s1 = g1[i] * rsqrtf(v1[i] + BN_EPS);
    g_bn1s[i] = s1; g_bn1t[i] = b1[i] - m1[i] * s1;
    float s2 = g2[i] * rsqrtf(v2[i] + BN_EPS);
    g_bn2s[i] = s2; g_bn2t[i] = b2[i] - m2[i] * s2;
}

__global__ void zero_cnt_kernel() {
    int i = blockIdx.x * blockDim.x + threadIdx.x;
    if (i < NTOT) g_cnt[i] = 0;
}

__global__ void count_deg_kernel(const int* __restrict__ adj) {
    int i = blockIdx.x * blockDim.x + threadIdx.x;
    if (i >= ETOT) return;
    int j = i / EDGES;
    int e = i - j * EDGES;
    int dst = adj[(size_t)j * 2 * EDGES + EDGES + e];
    atomicAdd(&g_cnt[j * NNODES + dst], 1);
}

__global__ void finalize_deg_kernel() {
    int i = blockIdx.x * blockDim.x + threadIdx.x;
    if (i >= NTOT) return;
    float d = (float)g_cnt[i] + 1.0f;
    g_dinv[i]   = rsqrtf(d);
    g_invdeg[i] = 1.0f / d;
}

// exclusive scan over g_cnt (NTOT values) -> g_start, g_cursor
__global__ void scanA_kernel() {
    __shared__ int sh[256];
    int i = blockIdx.x * 256 + threadIdx.x;
    int v = (i < NTOT) ? g_cnt[i] : 0;
    sh[threadIdx.x] = v;
    __syncthreads();
    for (int o = 1; o < 256; o <<= 1) {
        int t = (threadIdx.x >= o) ? sh[threadIdx.x - o] : 0;
        __syncthreads();
        sh[threadIdx.x] += t;
        __syncthreads();
    }
    if (i < NTOT) g_start[i] = sh[threadIdx.x] - v;
    if (threadIdx.x == 255) g_bsum[blockIdx.x] = sh[255];
}

__global__ void scanB_kernel(int nb) {
    __shared__ int sh[1024];
    int i = threadIdx.x;
    int v = (i < nb) ? g_bsum[i] : 0;
    sh[i] = v;
    __syncthreads();
    for (int o = 1; o < 1024; o <<= 1) {
        int t = (i >= o) ? sh[i - o] : 0;
        __syncthreads();
        sh[i] += t;
        __syncthreads();
    }
    g_bsum[i] = sh[i] - v;      // exclusive
}

__global__ void scanC_kernel() {
    int i = blockIdx.x * 256 + threadIdx.x;
    if (i < NTOT) {
        int s = g_start[i] + g_bsum[blockIdx.x];
        g_start[i] = s;
        g_cursor[i] = s;
    }
    if (i == 0) g_start[NTOT] = ETOT;
}

__global__ void scatter_kernel(const int* __restrict__ adj) {
    int i = blockIdx.x * blockDim.x + threadIdx.x;
    if (i >= ETOT) return;
    int j = i / EDGES;
    int e = i - j * EDGES;
    int src = adj[(size_t)j * 2 * EDGES + e];
    int dst = adj[(size_t)j * 2 * EDGES + EDGES + e];
    int pos = atomicAdd(&g_cursor[j * NNODES + dst], 1);
    g_esrc[pos] = src;
    g_ew[pos] = g_dinv[j * NNODES + src] * g_dinv[j * NNODES + dst];
}

__global__ void pack_wcat_kernel(const float* __restrict__ W_convs,
                                 const float* __restrict__ W_extra) {
    int i = blockIdx.x * blockDim.x + threadIdx.x;
    if (i >= FIN * NCAT) return;
    int k = i / NCAT;
    int c = i - k * NCAT;
    float v;
    if (c < 3 * HID) {
        int br = c / HID, h = c - br * HID;
        v = W_convs[(size_t)br * FIN * HID + (size_t)k * HID + h];
    } else {
        v = W_extra[(size_t)k * HID + (c - 3 * HID)];
    }
    g_Wcat[i] = v;
}

__global__ void transpose_wcls_kernel(const float* __restrict__ W_cls) {
    int i = blockIdx.x * blockDim.x + threadIdx.x;  // over NCLS*NCAT
    if (i >= NCLS * NCAT) return;
    int c = i / NCAT;
    int k = i - c * NCAT;
    g_Wt[i] = W_cls[(size_t)k * NCLS + c];
}

// ---------------- GEMM: 128x128x8 tile, 256 threads, 8x8/thread -------------
__global__ __launch_bounds__(256) void gemm128_kernel(
    const float* __restrict__ A, int lda,
    const float* __restrict__ B, int ldb,
    float* __restrict__ C, int ldc,
    int M, int K) {
    __shared__ float As[8][128];
    __shared__ float Bs[8][128];
    int tid = threadIdx.x;
    int bm = blockIdx.y * 128;
    int bn = blockIdx.x * 128;
    int arow = tid >> 1, acol = (tid & 1) * 4;
    int brow = tid >> 5, bcol = (tid & 31) * 4;
    int ty = tid >> 4, tx = tid & 15;

    float acc[8][8];
#pragma unroll
    for (int i = 0; i < 8; i++)
#pragma unroll
        for (int j = 0; j < 8; j++) acc[i][j] = 0.f;

    float4 av, bv;
    {
        int gm = bm + arow;
        av = (gm < M) ? *(const float4*)(A + (size_t)gm * lda + acol)
                      : make_float4(0.f, 0.f, 0.f, 0.f);
        bv = *(const float4*)(B + (size_t)brow * ldb + bn + bcol);
    }
    for (int k0 = 0; k0 < K; k0 += 8) {
        As[acol + 0][arow] = av.x;
        As[acol + 1][arow] = av.y;
        As[acol + 2][arow] = av.z;
        As[acol + 3][arow] = av.w;
        *(float4*)&Bs[brow][bcol] = bv;
        __syncthreads();
        if (k0 + 8 < K) {
            int gm = bm + arow;
            av = (gm < M) ? *(const float4*)(A + (size_t)gm * lda + k0 + 8 + acol)
                          : make_float4(0.f, 0.f, 0.f, 0.f);
            bv = *(const float4*)(B + (size_t)(k0 + 8 + brow) * ldb + bn + bcol);
        }
#pragma unroll
        for (int kk = 0; kk < 8; kk++) {
            float4 ra0 = *(const float4*)&As[kk][ty * 4];
            float4 ra1 = *(const float4*)&As[kk][64 + ty * 4];
            float4 rb0 = *(const float4*)&Bs[kk][tx * 4];
            float4 rb1 = *(const float4*)&Bs[kk][64 + tx * 4];
            float ra[8] = {ra0.x, ra0.y, ra0.z, ra0.w, ra1.x, ra1.y, ra1.z, ra1.w};
            float rb[8] = {rb0.x, rb0.y, rb0.z, rb0.w, rb1.x, rb1.y, rb1.z, rb1.w};
#pragma unroll
            for (int i = 0; i < 8; i++)
#pragma unroll
                for (int j = 0; j < 8; j++) acc[i][j] += ra[i] * rb[j];
        }
        __syncthreads();
    }
#pragma unroll
    for (int ih = 0; ih < 2; ih++)
#pragma unroll
        for (int i = 0; i < 4; i++) {
            int gm = bm + ih * 64 + ty * 4 + i;
            if (gm >= M) continue;
            float* cp = C + (size_t)gm * ldc + bn;
            int ai = ih * 4 + i;
            *(float4*)(cp + tx * 4)      = make_float4(acc[ai][0], acc[ai][1], acc[ai][2], acc[ai][3]);
            *(float4*)(cp + 64 + tx * 4) = make_float4(acc[ai][4], acc[ai][5], acc[ai][6], acc[ai][7]);
        }
}

// ---------------- CSR gather aggregation + fused epilogue -------------------
// mode 0: relu(acc + b) * mask[midx]
// mode 1: relu((acc+b)*bn1s + bn1t)
// mode 2: relu((acc+b)*bn2s + bn2t) * mask[midx]
__global__ __launch_bounds__(256) void agg_fused2_kernel(
    const int* __restrict__ start,
    const float* __restrict__ invdeg,
    const float* __restrict__ Hsrc, int ldH,
    float* __restrict__ Out, int ldO,
    int mode, int midx,
    const float* __restrict__ bias,
    const float* __restrict__ bns, const float* __restrict__ bnt) {
    float maskv = (midx >= 0) ? g_mask[midx] : 1.0f;
    int warp = (blockIdx.x * blockDim.x + threadIdx.x) >> 5;
    int lane = threadIdx.x & 31;
    if (warp >= NNODES) return;
    int n = warp;
    int h = lane * 8;

    const float4* sp = (const float4*)(Hsrc + (size_t)n * ldH + h);
    float idg = invdeg[n];
    float4 s0 = sp[0], s1 = sp[1];
    float4 a0 = make_float4(s0.x * idg, s0.y * idg, s0.z * idg, s0.w * idg);
    float4 a1 = make_float4(s1.x * idg, s1.y * idg, s1.z * idg, s1.w * idg);

    int e = start[n], eend = start[n + 1];
    for (; e + 2 <= eend; e += 2) {
        int sA = g_esrc[e], sB = g_esrc[e + 1];
        float wA = g_ew[e], wB = g_ew[e + 1];
        const float4* hA = (const float4*)(Hsrc + (size_t)sA * ldH + h);
        const float4* hB = (const float4*)(Hsrc + (size_t)sB * ldH + h);
        float4 vA0 = hA[0], vA1 = hA[1];
        float4 vB0 = hB[0], vB1 = hB[1];
        a0.x += wA * vA0.x + wB * vB0.x;
        a0.y += wA * vA0.y + wB * vB0.y;
        a0.z += wA * vA0.z + wB * vB0.z;
        a0.w += wA * vA0.w + wB * vB0.w;
        a1.x += wA * vA1.x + wB * vB1.x;
        a1.y += wA * vA1.y + wB * vB1.y;
        a1.z += wA * vA1.z + wB * vB1.z;
        a1.w += wA * vA1.w + wB * vB1.w;
    }
    if (e < eend) {
        int sA = g_esrc[e];
        float wA = g_ew[e];
        const float4* hA = (const float4*)(Hsrc + (size_t)sA * ldH + h);
        float4 vA0 = hA[0], vA1 = hA[1];
        a0.x += wA * vA0.x; a0.y += wA * vA0.y; a0.z += wA * vA0.z; a0.w += wA * vA0.w;
        a1.x += wA * vA1.x; a1.y += wA * vA1.y; a1.z += wA * vA1.z; a1.w += wA * vA1.w;
    }

    float4 b0 = *(const float4*)(bias + h);
    float4 b1 = *(const float4*)(bias + h + 4);
    a0.x += b0.x; a0.y += b0.y; a0.z += b0.z; a0.w += b0.w;
    a1.x += b1.x; a1.y += b1.y; a1.z += b1.z; a1.w += b1.w;
    if (mode != 0) {
        float4 sc0 = *(const float4*)(bns + h);
        float4 sc1 = *(const float4*)(bns + h + 4);
        float4 t0 = *(const float4*)(bnt + h);
        float4 t1 = *(const float4*)(bnt + h + 4);
        a0.x = a0.x * sc0.x + t0.x; a0.y = a0.y * sc0.y + t0.y;
        a0.z = a0.z * sc0.z + t0.z; a0.w = a0.w * sc0.w + t0.w;
        a1.x = a1.x * sc1.x + t1.x; a1.y = a1.y * sc1.y + t1.y;
        a1.z = a1.z * sc1.z + t1.z; a1.w = a1.w * sc1.w + t1.w;
    }
    a0.x = fmaxf(a0.x, 0.f) * maskv; a0.y = fmaxf(a0.y, 0.f) * maskv;
    a0.z = fmaxf(a0.z, 0.f) * maskv; a0.w = fmaxf(a0.w, 0.f) * maskv;
    a1.x = fmaxf(a1.x, 0.f) * maskv; a1.y = fmaxf(a1.y, 0.f) * maskv;
    a1.z = fmaxf(a1.z, 0.f) * maskv; a1.w = fmaxf(a1.w, 0.f) * maskv;

    float4* op = (float4*)(Out + (size_t)n * ldO + h);
    op[0] = a0;
    op[1] = a1;
}

// ---------------- fused classifier + log_softmax (warp per node) ------------
__global__ __launch_bounds__(256) void cls_lsm_kernel(const float* __restrict__ b_cls,
                                                      float* __restrict__ out) {
    __shared__ float slog[8][NCLS];
    int warp = (blockIdx.x * blockDim.x + threadIdx.x) >> 5;
    int lane = threadIdx.x & 31;
    int wl = threadIdx.x >> 5;
    if (warp >= NNODES) return;

    const float4* row = (const float4*)(g_AGG + (size_t)warp * NCAT);
    float4 r[8];
#pragma unroll
    for (int i = 0; i < 8; i++) r[i] = row[i * 32 + lane];

    for (int c = 0; c < NCLS; c++) {
        const float4* wt = (const float4*)(g_Wt + (size_t)c * NCAT);
        float acc = 0.f;
#pragma unroll
        for (int i = 0; i < 8; i++) {
            float4 q = wt[i * 32 + lane];
            acc += r[i].x * q.x + r[i].y * q.y + r[i].z * q.z + r[i].w * q.w;
        }
#pragma unroll
        for (int o = 16; o > 0; o >>= 1) acc += __shfl_xor_sync(0xffffffffu, acc, o);
        if (lane == 0) slog[wl][c] = acc + b_cls[c];
    }
    __syncwarp();
    int l2 = lane + 32;
    float v0 = (lane < NCLS) ? slog[wl][lane] : -1e30f;   // classes 0..31
    float v1 = (l2 < NCLS)   ? slog[wl][l2]   : -1e30f;   // classes 32..39
    float m = fmaxf(v0, v1);
#pragma unroll
    for (int o = 16; o > 0; o >>= 1) m = fmaxf(m, __shfl_xor_sync(0xffffffffu, m, o));
    float s = ((lane < NCLS) ? expf(v0 - m) : 0.f) + ((l2 < NCLS) ? expf(v1 - m) : 0.f);
#pragma unroll
    for (int o = 16; o > 0; o >>= 1) s += __shfl_xor_sync(0xffffffffu, s, o);
    float L = m + logf(s);
    if (lane < NCLS) out[(size_t)warp * NCLS + lane] = v0 - L;
    if (l2 < NCLS)   out[(size_t)warp * NCLS + l2]   = v1 - L;
}

__global__ void tail_kernel(float* out, int startI, int total) {
    int i = startI + blockIdx.x * blockDim.x + threadIdx.x;
    if (i < total) out[i] = 0.f;
}

// ---------------- launch ----------------------------------------------------
extern "C" void kernel_launch(void* const* d_in, const int* in_sizes, int n_in,
                              void* d_out, int out_size) {
    const float* x        = (const float*)d_in[0];
    const int*   adj      = (const int*)d_in[1];
    const float* W_convs  = (const float*)d_in[2];
    const float* b_convs  = (const float*)d_in[3];
    const float* W_extra  = (const float*)d_in[4];
    const float* b_extra  = (const float*)d_in[5];
    const float* bn1g     = (const float*)d_in[6];
    const float* bn1b     = (const float*)d_in[7];
    const float* bn1m     = (const float*)d_in[8];
    const float* bn1v     = (const float*)d_in[9];
    const float* W_extra2 = (const float*)d_in[10];
    const float* b_extra2 = (const float*)d_in[11];
    const float* bn2g     = (const float*)d_in[12];
    const float* bn2b     = (const float*)d_in[13];
    const float* bn2m     = (const float*)d_in[14];
    const float* bn2v     = (const float*)d_in[15];
    const float* att      = (const float*)d_in[16];
    const float* W_cls    = (const float*)d_in[17];
    const float* b_cls    = (const float*)d_in[18];
    float* out = (float*)d_out;

    float *p_T1, *p_AGG, *p_invdeg, *p_Wcat;
    float *p_bn1s, *p_bn1t, *p_bn2s, *p_bn2t;
    int *p_start;
    cudaGetSymbolAddress((void**)&p_T1,    g_T1);
    cudaGetSymbolAddress((void**)&p_AGG,   g_AGG);
    cudaGetSymbolAddress((void**)&p_invdeg,g_invdeg);
    cudaGetSymbolAddress((void**)&p_Wcat,  g_Wcat);
    cudaGetSymbolAddress((void**)&p_start, g_start);
    cudaGetSymbolAddress((void**)&p_bn1s,  g_bn1s);
    cudaGetSymbolAddress((void**)&p_bn1t,  g_bn1t);
    cudaGetSymbolAddress((void**)&p_bn2s,  g_bn2s);
    cudaGetSymbolAddress((void**)&p_bn2t,  g_bn2t);

    const int SCAN_BLOCKS = (NTOT + 255) / 256;   // 782

    // ---- prep ----
    mask_kernel<<<1, 32>>>(att);
    bnfold_kernel<<<1, 256>>>(bn1g, bn1b, bn1m, bn1v, bn2g, bn2b, bn2m, bn2v);
    zero_cnt_kernel<<<SCAN_BLOCKS, 256>>>();
    count_deg_kernel<<<(ETOT + 255) / 256, 256>>>(adj);
    finalize_deg_kernel<<<SCAN_BLOCKS, 256>>>();
    scanA_kernel<<<SCAN_BLOCKS, 256>>>();
    scanB_kernel<<<1, 1024>>>(SCAN_BLOCKS);
    scanC_kernel<<<SCAN_BLOCKS, 256>>>();
    scatter_kernel<<<(ETOT + 255) / 256, 256>>>(adj);
    pack_wcat_kernel<<<(FIN * NCAT + 255) / 256, 256>>>(W_convs, W_extra);
    transpose_wcls_kernel<<<(NCLS * NCAT + 255) / 256, 256>>>(W_cls);

    // ---- GEMM1: T1 = x @ Wcat  [50000 x 1024] ----
    {
        dim3 grid(NCAT / 128, (NNODES + 127) / 128);
        gemm128_kernel<<<grid, 256>>>(x, FIN, p_Wcat, NCAT, p_T1, NCAT, NNODES, FIN);
    }

    // ---- aggregations (gather, fused epilogue) ----
    int agg_blocks = (NNODES * 32 + 255) / 256;
    for (int s = 0; s < 3; s++) {
        int a = s + 1;
        agg_fused2_kernel<<<agg_blocks, 256>>>(
            p_start + a * NNODES, p_invdeg + a * NNODES,
            p_T1 + s * HID, NCAT,
            p_AGG + s * HID, NCAT,
            0, s, b_convs + s * HID, nullptr, nullptr);
    }
    // extra layer 1 on adj[0]: e1 -> AGG slice3
    agg_fused2_kernel<<<agg_blocks, 256>>>(
        p_start, p_invdeg,
        p_T1 + 3 * HID, NCAT,
        p_AGG + 3 * HID, NCAT,
        1, -1, b_extra, p_bn1s, p_bn1t);
    // GEMM2: T2 = e1 @ W_extra2, stored into T1 slice3
    {
        dim3 grid(HID / 128, (NNODES + 127) / 128);
        gemm128_kernel<<<grid, 256>>>(p_AGG + 3 * HID, NCAT, W_extra2, HID,
                                      p_T1 + 3 * HID, NCAT, NNODES, HID);
    }
    // extra layer 2 on adj[0]: final extra branch into AGG slice3
    agg_fused2_kernel<<<agg_blocks, 256>>>(
        p_start, p_invdeg,
        p_T1 + 3 * HID, NCAT,
        p_AGG + 3 * HID, NCAT,
        2, 3, b_extra2, p_bn2s, p_bn2t);

    // ---- classifier + log_softmax ----
    cls_lsm_kernel<<<(NNODES * 32 + 255) / 256, 256>>>(b_cls, out);
    int tail = out_size - NNODES * NCLS;
    if (tail > 0)
        tail_kernel<<<(tail + 255) / 256, 256>>>(out, NNODES * NCLS, out_size);
}

// round 4
// speedup vs baseline: 5.0426x; 1.1962x over previous
#include <cuda_runtime.h>
#include <cuda_bf16.h>
#include <cstdint>

#define NNODES 50000
#define EDGES 800000
#define FIN 256
#define HID 256
#define NCAT 1024
#define NCLS 40
#define BN_EPS 1e-5f
#define NTOT (4 * NNODES)
#define ETOT (4 * EDGES)

// ---------------- scratch (static device globals) ---------------------------
__device__ float g_T1[(size_t)NNODES * NCAT];     // x @ Wcat; slice3 later holds T2
__device__ float g_AGG[(size_t)NNODES * NCAT];    // aggregation output -> FINAL
__device__ int   g_cnt[NTOT];
__device__ float g_dinv[NTOT];
__device__ float g_invdeg[NTOT];
__device__ int   g_start[NTOT + 1];
__device__ int   g_cursor[NTOT];
__device__ int   g_bsum[1024];
__device__ int   g_esrc[ETOT];
__device__ float g_ew[ETOT];
__device__ float g_Wt[NCLS * NCAT];
__device__ float g_mask[4];
__device__ float g_bn1s[HID], g_bn1t[HID], g_bn2s[HID], g_bn2t[HID];
// bf16 split operands
__device__ __nv_bfloat16 g_xhi[(size_t)NNODES * FIN];
__device__ __nv_bfloat16 g_xlo[(size_t)NNODES * FIN];
__device__ __nv_bfloat16 g_Whi[FIN * NCAT];
__device__ __nv_bfloat16 g_Wlo[FIN * NCAT];
__device__ __nv_bfloat16 g_W2hi[HID * HID];
__device__ __nv_bfloat16 g_W2lo[HID * HID];
__device__ __nv_bfloat16 g_e1hi[(size_t)NNODES * HID];
__device__ __nv_bfloat16 g_e1lo[(size_t)NNODES * HID];

// ---------------- tiny prep kernels -----------------------------------------
__global__ void mask_kernel(const float* __restrict__ att) {
    if (threadIdx.x == 0) {
        float m = att[0];
        for (int i = 1; i < 4; i++) m = fmaxf(m, att[i]);
        float s = 0.f, e[4];
        for (int i = 0; i < 4; i++) { e[i] = expf(att[i] - m); s += e[i]; }
        for (int i = 0; i < 4; i++) g_mask[i] = e[i] / s;
    }
}

__global__ void bnfold_kernel(const float* g1, const float* b1, const float* m1, const float* v1,
                              const float* g2, const float* b2, const float* m2, const float* v2) {
    int i = blockIdx.x * blockDim.x + threadIdx.x;
    if (i >= HID) return;
    float s1 = g1[i] * rsqrtf(v1[i] + BN_EPS);
    g_bn1s[i] = s1; g_bn1t[i] = b1[i] - m1[i] * s1;
    float s2 = g2[i] * rsqrtf(v2[i] + BN_EPS);
    g_bn2s[i] = s2; g_bn2t[i] = b2[i] - m2[i] * s2;
}

__global__ void zero_cnt_kernel() {
    int i = blockIdx.x * blockDim.x + threadIdx.x;
    if (i < NTOT) g_cnt[i] = 0;
}

__global__ void count_deg_kernel(const int* __restrict__ adj) {
    int i = blockIdx.x * blockDim.x + threadIdx.x;
    if (i >= ETOT) return;
    int j = i / EDGES;
    int e = i - j * EDGES;
    int dst = adj[(size_t)j * 2 * EDGES + EDGES + e];
    atomicAdd(&g_cnt[j * NNODES + dst], 1);
}

__global__ void finalize_deg_kernel() {
    int i = blockIdx.x * blockDim.x + threadIdx.x;
    if (i >= NTOT) return;
    float d = (float)g_cnt[i] + 1.0f;
    g_dinv[i]   = rsqrtf(d);
    g_invdeg[i] = 1.0f / d;
}

__global__ void scanA_kernel() {
    __shared__ int sh[256];
    int i = blockIdx.x * 256 + threadIdx.x;
    int v = (i < NTOT) ? g_cnt[i] : 0;
    sh[threadIdx.x] = v;
    __syncthreads();
    for (int o = 1; o < 256; o <<= 1) {
        int t = (threadIdx.x >= o) ? sh[threadIdx.x - o] : 0;
        __syncthreads();
        sh[threadIdx.x] += t;
        __syncthreads();
    }
    if (i < NTOT) g_start[i] = sh[threadIdx.x] - v;
    if (threadIdx.x == 255) g_bsum[blockIdx.x] = sh[255];
}

__global__ void scanB_kernel(int nb) {
    __shared__ int sh[1024];
    int i = threadIdx.x;
    int v = (i < nb) ? g_bsum[i] : 0;
    sh[i] = v;
    __syncthreads();
    for (int o = 1; o < 1024; o <<= 1) {
        int t = (i >= o) ? sh[i - o] : 0;
        __syncthreads();
        sh[i] += t;
        __syncthreads();
    }
    g_bsum[i] = sh[i] - v;
}

__global__ void scanC_kernel() {
    int i = blockIdx.x * 256 + threadIdx.x;
    if (i < NTOT) {
        int s = g_start[i] + g_bsum[blockIdx.x];
        g_start[i] = s;
        g_cursor[i] = s;
    }
    if (i == 0) g_start[NTOT] = ETOT;
}

__global__ void scatter_kernel(const int* __restrict__ adj) {
    int i = blockIdx.x * blockDim.x + threadIdx.x;
    if (i >= ETOT) return;
    int j = i / EDGES;
    int e = i - j * EDGES;
    int src = adj[(size_t)j * 2 * EDGES + e];
    int dst = adj[(size_t)j * 2 * EDGES + EDGES + e];
    int pos = atomicAdd(&g_cursor[j * NNODES + dst], 1);
    g_esrc[pos] = src;
    g_ew[pos] = g_dinv[j * NNODES + src] * g_dinv[j * NNODES + dst];
}

// pack Wcat (fp32 concat of W_convs + W_extra) directly into bf16 hi/lo
__global__ void pack_wsplit_kernel(const float* __restrict__ W_convs,
                                   const float* __restrict__ W_extra) {
    int i = blockIdx.x * blockDim.x + threadIdx.x;
    if (i >= FIN * NCAT) return;
    int k = i / NCAT;
    int c = i - k * NCAT;
    float v;
    if (c < 3 * HID) {
        int br = c / HID, h = c - br * HID;
        v = W_convs[(size_t)br * FIN * HID + (size_t)k * HID + h];
    } else {
        v = W_extra[(size_t)k * HID + (c - 3 * HID)];
    }
    __nv_bfloat16 h16 = __float2bfloat16(v);
    g_Whi[i] = h16;
    g_Wlo[i] = __float2bfloat16(v - __bfloat162float(h16));
}

__global__ void split_dense_kernel(const float* __restrict__ src,
                                   __nv_bfloat16* __restrict__ hi,
                                   __nv_bfloat16* __restrict__ lo, int n) {
    int i = blockIdx.x * blockDim.x + threadIdx.x;
    if (i >= n) return;
    float v = src[i];
    __nv_bfloat16 h16 = __float2bfloat16(v);
    hi[i] = h16;
    lo[i] = __float2bfloat16(v - __bfloat162float(h16));
}

// e1 lives in g_AGG slice3 (row stride NCAT); emit dense [N][256] hi/lo
__global__ void split_e1_kernel() {
    int i = blockIdx.x * blockDim.x + threadIdx.x;
    if (i >= NNODES * HID) return;
    int n = i >> 8;
    int c = i & 255;
    float v = g_AGG[(size_t)n * NCAT + 3 * HID + c];
    __nv_bfloat16 h16 = __float2bfloat16(v);
    g_e1hi[i] = h16;
    g_e1lo[i] = __float2bfloat16(v - __bfloat162float(h16));
}

__global__ void transpose_wcls_kernel(const float* __restrict__ W_cls) {
    int i = blockIdx.x * blockDim.x + threadIdx.x;
    if (i >= NCLS * NCAT) return;
    int c = i / NCAT;
    int k = i - c * NCAT;
    g_Wt[i] = W_cls[(size_t)k * NCLS + c];
}

// ---------------- bf16 tensor-core GEMM (3-term split) -----------------------
// C[M, 128*gridX] = Ahi@Bhi + Ahi@Blo + Alo@Bhi   (fp32 accumulate)
// A*: [M][256] bf16 dense. B*: [256][ldb] bf16. C: fp32 [M][ldc].
__device__ __forceinline__ uint32_t smem_u32(const void* p) {
    return (uint32_t)__cvta_generic_to_shared(p);
}
__device__ __forceinline__ void ldsm_x4(uint32_t* r, uint32_t addr) {
    asm volatile("ldmatrix.sync.aligned.m8n8.x4.shared.b16 {%0,%1,%2,%3},[%4];"
                 : "=r"(r[0]), "=r"(r[1]), "=r"(r[2]), "=r"(r[3]) : "r"(addr));
}
__device__ __forceinline__ void ldsm_x4_t(uint32_t* r, uint32_t addr) {
    asm volatile("ldmatrix.sync.aligned.m8n8.x4.trans.shared.b16 {%0,%1,%2,%3},[%4];"
                 : "=r"(r[0]), "=r"(r[1]), "=r"(r[2]), "=r"(r[3]) : "r"(addr));
}
__device__ __forceinline__ void mma16816(float* c, const uint32_t* a, const uint32_t* b) {
    asm volatile(
        "mma.sync.aligned.m16n8k16.row.col.f32.bf16.bf16.f32 "
        "{%0,%1,%2,%3},{%4,%5,%6,%7},{%8,%9},{%0,%1,%2,%3};"
        : "+f"(c[0]), "+f"(c[1]), "+f"(c[2]), "+f"(c[3])
        : "r"(a[0]), "r"(a[1]), "r"(a[2]), "r"(a[3]), "r"(b[0]), "r"(b[1]));
}

#define A_STRIDE 24
#define B_STRIDE 136
__global__ __launch_bounds__(256) void gemm_bf16_kernel(
    const __nv_bfloat16* __restrict__ Ahi, const __nv_bfloat16* __restrict__ Alo,
    const __nv_bfloat16* __restrict__ Bhi, const __nv_bfloat16* __restrict__ Blo,
    int ldb, float* __restrict__ C, int ldc, int M) {
    __shared__ __nv_bfloat16 As[128][A_STRIDE];
    __shared__ __nv_bfloat16 Bs[16][B_STRIDE];
    int tid = threadIdx.x;
    int lane = tid & 31, wid = tid >> 5;
    int wm = wid & 3, wn = wid >> 2;          // warp tile: 32(M) x 64(N)
    int bm = blockIdx.y * 128, bn = blockIdx.x * 128;

    // global->smem mapping
    int am = tid >> 1, ak = (tid & 1) * 8;    // A: 128 rows x 16 k, uint4/thread
    int bk = tid >> 4, bc = (tid & 15) * 8;   // B: 16 rows x 128 n, uint4/thread
    int gm_l = bm + am;
    bool rowOK = gm_l < M;

    float c[2][8][4];
#pragma unroll
    for (int t = 0; t < 2; t++)
#pragma unroll
        for (int j = 0; j < 8; j++)
#pragma unroll
            for (int q = 0; q < 4; q++) c[t][j][q] = 0.f;

    // ldmatrix addresses
    uint32_t aAddr0 = smem_u32(&As[wm * 32 + (lane & 15)][(lane >> 4) * 8]);
    uint32_t aAddr1 = aAddr0 + 16 * A_STRIDE * 2;
    int bRow = (lane & 7) + ((lane >> 3) & 1) * 8;
    uint32_t bAddrBase = smem_u32(&Bs[bRow][(lane >> 4) * 8 + wn * 64]);

    uint4 av, bv;
    {   // prefetch kt = 0 (seg 0: hi*hi)
        av = rowOK ? *(const uint4*)(Ahi + (size_t)gm_l * FIN + ak)
                   : make_uint4(0, 0, 0, 0);
        bv = *(const uint4*)(Bhi + (size_t)bk * ldb + bn + bc);
    }
    const int KT = 48;                         // 3 segs * 256 / 16
    for (int kt = 0; kt < KT; kt++) {
        *(uint4*)&As[am][ak] = av;
        *(uint4*)&Bs[bk][bc] = bv;
        __syncthreads();
        if (kt + 1 < KT) {
            int k0 = (kt + 1) * 16;
            int seg = k0 >> 8, kk = k0 & 255;
            const __nv_bfloat16* Aseg = (seg < 2) ? Ahi : Alo;
            const __nv_bfloat16* Bseg = (seg == 1) ? Blo : Bhi;
            av = rowOK ? *(const uint4*)(Aseg + (size_t)gm_l * FIN + kk + ak)
                       : make_uint4(0, 0, 0, 0);
            bv = *(const uint4*)(Bseg + (size_t)(kk + bk) * ldb + bn + bc);
        }
        uint32_t a[2][4];
        ldsm_x4(a[0], aAddr0);
        ldsm_x4(a[1], aAddr1);
        uint32_t bf[4][4];
#pragma unroll
        for (int j4 = 0; j4 < 4; j4++)
            ldsm_x4_t(bf[j4], bAddrBase + j4 * 16 * 2);
#pragma unroll
        for (int t = 0; t < 2; t++)
#pragma unroll
            for (int j = 0; j < 8; j++)
                mma16816(c[t][j], a[t], &bf[j >> 1][(j & 1) * 2]);
        __syncthreads();
    }

    // store C
    int r = lane >> 2, cc = (lane & 3) * 2;
#pragma unroll
    for (int t = 0; t < 2; t++) {
        int m0 = bm + wm * 32 + t * 16;
#pragma unroll
        for (int j = 0; j < 8; j++) {
            int n0 = bn + wn * 64 + j * 8;
            if (m0 + r < M)
                *(float2*)(C + (size_t)(m0 + r) * ldc + n0 + cc) =
                    make_float2(c[t][j][0], c[t][j][1]);
            if (m0 + r + 8 < M)
                *(float2*)(C + (size_t)(m0 + r + 8) * ldc + n0 + cc) =
                    make_float2(c[t][j][2], c[t][j][3]);
        }
    }
}

// ---------------- CSR gather aggregation + fused epilogue -------------------
__global__ __launch_bounds__(256) void agg_fused2_kernel(
    const int* __restrict__ start,
    const float* __restrict__ invdeg,
    const float* __restrict__ Hsrc, int ldH,
    float* __restrict__ Out, int ldO,
    int mode, int midx,
    const float* __restrict__ bias,
    const float* __restrict__ bns, const float* __restrict__ bnt) {
    float maskv = (midx >= 0) ? g_mask[midx] : 1.0f;
    int warp = (blockIdx.x * blockDim.x + threadIdx.x) >> 5;
    int lane = threadIdx.x & 31;
    if (warp >= NNODES) return;
    int n = warp;
    int h = lane * 8;

    const float4* sp = (const float4*)(Hsrc + (size_t)n * ldH + h);
    float idg = invdeg[n];
    float4 s0 = sp[0], s1 = sp[1];
    float4 a0 = make_float4(s0.x * idg, s0.y * idg, s0.z * idg, s0.w * idg);
    float4 a1 = make_float4(s1.x * idg, s1.y * idg, s1.z * idg, s1.w * idg);

    int e = start[n], eend = start[n + 1];
    for (; e + 2 <= eend; e += 2) {
        int sA = g_esrc[e], sB = g_esrc[e + 1];
        float wA = g_ew[e], wB = g_ew[e + 1];
        const float4* hA = (const float4*)(Hsrc + (size_t)sA * ldH + h);
        const float4* hB = (const float4*)(Hsrc + (size_t)sB * ldH + h);
        float4 vA0 = hA[0], vA1 = hA[1];
        float4 vB0 = hB[0], vB1 = hB[1];
        a0.x += wA * vA0.x + wB * vB0.x;
        a0.y += wA * vA0.y + wB * vB0.y;
        a0.z += wA * vA0.z + wB * vB0.z;
        a0.w += wA * vA0.w + wB * vB0.w;
        a1.x += wA * vA1.x + wB * vB1.x;
        a1.y += wA * vA1.y + wB * vB1.y;
        a1.z += wA * vA1.z + wB * vB1.z;
        a1.w += wA * vA1.w + wB * vB1.w;
    }
    if (e < eend) {
        int sA = g_esrc[e];
        float wA = g_ew[e];
        const float4* hA = (const float4*)(Hsrc + (size_t)sA * ldH + h);
        float4 vA0 = hA[0], vA1 = hA[1];
        a0.x += wA * vA0.x; a0.y += wA * vA0.y; a0.z += wA * vA0.z; a0.w += wA * vA0.w;
        a1.x += wA * vA1.x; a1.y += wA * vA1.y; a1.z += wA * vA1.z; a1.w += wA * vA1.w;
    }

    float4 b0 = *(const float4*)(bias + h);
    float4 b1 = *(const float4*)(bias + h + 4);
    a0.x += b0.x; a0.y += b0.y; a0.z += b0.z; a0.w += b0.w;
    a1.x += b1.x; a1.y += b1.y; a1.z += b1.z; a1.w += b1.w;
    if (mode != 0) {
        float4 sc0 = *(const float4*)(bns + h);
        float4 sc1 = *(const float4*)(bns + h + 4);
        float4 t0 = *(const float4*)(bnt + h);
        float4 t1 = *(const float4*)(bnt + h + 4);
        a0.x = a0.x * sc0.x + t0.x; a0.y = a0.y * sc0.y + t0.y;
        a0.z = a0.z * sc0.z + t0.z; a0.w = a0.w * sc0.w + t0.w;
        a1.x = a1.x * sc1.x + t1.x; a1.y = a1.y * sc1.y + t1.y;
        a1.z = a1.z * sc1.z + t1.z; a1.w = a1.w * sc1.w + t1.w;
    }
    a0.x = fmaxf(a0.x, 0.f) * maskv; a0.y = fmaxf(a0.y, 0.f) * maskv;
    a0.z = fmaxf(a0.z, 0.f) * maskv; a0.w = fmaxf(a0.w, 0.f) * maskv;
    a1.x = fmaxf(a1.x, 0.f) * maskv; a1.y = fmaxf(a1.y, 0.f) * maskv;
    a1.z = fmaxf(a1.z, 0.f) * maskv; a1.w = fmaxf(a1.w, 0.f) * maskv;

    float4* op = (float4*)(Out + (size_t)n * ldO + h);
    op[0] = a0;
    op[1] = a1;
}

// ---------------- fused classifier + log_softmax (warp per node) ------------
__global__ __launch_bounds__(256) void cls_lsm_kernel(const float* __restrict__ b_cls,
                                                      float* __restrict__ out) {
    __shared__ float slog[8][NCLS];
    int warp = (blockIdx.x * blockDim.x + threadIdx.x) >> 5;
    int lane = threadIdx.x & 31;
    int wl = threadIdx.x >> 5;
    if (warp >= NNODES) return;

    const float4* row = (const float4*)(g_AGG + (size_t)warp * NCAT);
    float4 r[8];
#pragma unroll
    for (int i = 0; i < 8; i++) r[i] = row[i * 32 + lane];

    for (int c = 0; c < NCLS; c++) {
        const float4* wt = (const float4*)(g_Wt + (size_t)c * NCAT);
        float acc = 0.f;
#pragma unroll
        for (int i = 0; i < 8; i++) {
            float4 q = wt[i * 32 + lane];
            acc += r[i].x * q.x + r[i].y * q.y + r[i].z * q.z + r[i].w * q.w;
        }
#pragma unroll
        for (int o = 16; o > 0; o >>= 1) acc += __shfl_xor_sync(0xffffffffu, acc, o);
        if (lane == 0) slog[wl][c] = acc + b_cls[c];
    }
    __syncwarp();
    int l2 = lane + 32;
    float v0 = (lane < NCLS) ? slog[wl][lane] : -1e30f;
    float v1 = (l2 < NCLS)   ? slog[wl][l2]   : -1e30f;
    float m = fmaxf(v0, v1);
#pragma unroll
    for (int o = 16; o > 0; o >>= 1) m = fmaxf(m, __shfl_xor_sync(0xffffffffu, m, o));
    float s = ((lane < NCLS) ? expf(v0 - m) : 0.f) + ((l2 < NCLS) ? expf(v1 - m) : 0.f);
#pragma unroll
    for (int o = 16; o > 0; o >>= 1) s += __shfl_xor_sync(0xffffffffu, s, o);
    float L = m + logf(s);
    if (lane < NCLS) out[(size_t)warp * NCLS + lane] = v0 - L;
    if (l2 < NCLS)   out[(size_t)warp * NCLS + l2]   = v1 - L;
}

__global__ void tail_kernel(float* out, int startI, int total) {
    int i = startI + blockIdx.x * blockDim.x + threadIdx.x;
    if (i < total) out[i] = 0.f;
}

// ---------------- launch ----------------------------------------------------
extern "C" void kernel_launch(void* const* d_in, const int* in_sizes, int n_in,
                              void* d_out, int out_size) {
    const float* x        = (const float*)d_in[0];
    const int*   adj      = (const int*)d_in[1];
    const float* W_convs  = (const float*)d_in[2];
    const float* b_convs  = (const float*)d_in[3];
    const float* W_extra  = (const float*)d_in[4];
    const float* b_extra  = (const float*)d_in[5];
    const float* bn1g     = (const float*)d_in[6];
    const float* bn1b     = (const float*)d_in[7];
    const float* bn1m     = (const float*)d_in[8];
    const float* bn1v     = (const float*)d_in[9];
    const float* W_extra2 = (const float*)d_in[10];
    const float* b_extra2 = (const float*)d_in[11];
    const float* bn2g     = (const float*)d_in[12];
    const float* bn2b     = (const float*)d_in[13];
    const float* bn2m     = (const float*)d_in[14];
    const float* bn2v     = (const float*)d_in[15];
    const float* att      = (const float*)d_in[16];
    const float* W_cls    = (const float*)d_in[17];
    const float* b_cls    = (const float*)d_in[18];
    float* out = (float*)d_out;

    float *p_T1, *p_AGG, *p_invdeg;
    float *p_bn1s, *p_bn1t, *p_bn2s, *p_bn2t;
    int *p_start;
    __nv_bfloat16 *p_xhi, *p_xlo, *p_Whi, *p_Wlo, *p_W2hi, *p_W2lo, *p_e1hi, *p_e1lo;
    cudaGetSymbolAddress((void**)&p_T1,    g_T1);
    cudaGetSymbolAddress((void**)&p_AGG,   g_AGG);
    cudaGetSymbolAddress((void**)&p_invdeg,g_invdeg);
    cudaGetSymbolAddress((void**)&p_start, g_start);
    cudaGetSymbolAddress((void**)&p_bn1s,  g_bn1s);
    cudaGetSymbolAddress((void**)&p_bn1t,  g_bn1t);
    cudaGetSymbolAddress((void**)&p_bn2s,  g_bn2s);
    cudaGetSymbolAddress((void**)&p_bn2t,  g_bn2t);
    cudaGetSymbolAddress((void**)&p_xhi,   g_xhi);
    cudaGetSymbolAddress((void**)&p_xlo,   g_xlo);
    cudaGetSymbolAddress((void**)&p_Whi,   g_Whi);
    cudaGetSymbolAddress((void**)&p_Wlo,   g_Wlo);
    cudaGetSymbolAddress((void**)&p_W2hi,  g_W2hi);
    cudaGetSymbolAddress((void**)&p_W2lo,  g_W2lo);
    cudaGetSymbolAddress((void**)&p_e1hi,  g_e1hi);
    cudaGetSymbolAddress((void**)&p_e1lo,  g_e1lo);

    const int SCAN_BLOCKS = (NTOT + 255) / 256;

    // ---- prep ----
    mask_kernel<<<1, 32>>>(att);
    bnfold_kernel<<<1, 256>>>(bn1g, bn1b, bn1m, bn1v, bn2g, bn2b, bn2m, bn2v);
    zero_cnt_kernel<<<SCAN_BLOCKS, 256>>>();
    count_deg_kernel<<<(ETOT + 255) / 256, 256>>>(adj);
    finalize_deg_kernel<<<SCAN_BLOCKS, 256>>>();
    scanA_kernel<<<SCAN_BLOCKS, 256>>>();
    scanB_kernel<<<1, 1024>>>(SCAN_BLOCKS);
    scanC_kernel<<<SCAN_BLOCKS, 256>>>();
    scatter_kernel<<<(ETOT + 255) / 256, 256>>>(adj);
    pack_wsplit_kernel<<<(FIN * NCAT + 255) / 256, 256>>>(W_convs, W_extra);
    split_dense_kernel<<<(NNODES * FIN + 255) / 256, 256>>>(x, p_xhi, p_xlo, NNODES * FIN);
    split_dense_kernel<<<(HID * HID + 255) / 256, 256>>>(W_extra2, p_W2hi, p_W2lo, HID * HID);
    transpose_wcls_kernel<<<(NCLS * NCAT + 255) / 256, 256>>>(W_cls);

    // ---- GEMM1 (tensor): T1 = x @ Wcat  [50000 x 1024] ----
    {
        dim3 grid(NCAT / 128, (NNODES + 127) / 128);
        gemm_bf16_kernel<<<grid, 256>>>(p_xhi, p_xlo, p_Whi, p_Wlo, NCAT,
                                        p_T1, NCAT, NNODES);
    }

    // ---- aggregations (gather, fused epilogue) ----
    int agg_blocks = (NNODES * 32 + 255) / 256;
    for (int s = 0; s < 3; s++) {
        int a = s + 1;
        agg_fused2_kernel<<<agg_blocks, 256>>>(
            p_start + a * NNODES, p_invdeg + a * NNODES,
            p_T1 + s * HID, NCAT,
            p_AGG + s * HID, NCAT,
            0, s, b_convs + s * HID, nullptr, nullptr);
    }
    // extra layer 1 on adj[0]: e1 -> AGG slice3
    agg_fused2_kernel<<<agg_blocks, 256>>>(
        p_start, p_invdeg,
        p_T1 + 3 * HID, NCAT,
        p_AGG + 3 * HID, NCAT,
        1, -1, b_extra, p_bn1s, p_bn1t);
    // split e1 to bf16 hi/lo
    split_e1_kernel<<<(NNODES * HID + 255) / 256, 256>>>();
    // GEMM2 (tensor): T2 = e1 @ W_extra2, stored into T1 slice3
    {
        dim3 grid(HID / 128, (NNODES + 127) / 128);
        gemm_bf16_kernel<<<grid, 256>>>(p_e1hi, p_e1lo, p_W2hi, p_W2lo, HID,
                                        p_T1 + 3 * HID, NCAT, NNODES);
    }
    // extra layer 2 on adj[0]: final extra branch into AGG slice3
    agg_fused2_kernel<<<agg_blocks, 256>>>(
        p_start, p_invdeg,
        p_T1 + 3 * HID, NCAT,
        p_AGG + 3 * HID, NCAT,
        2, 3, b_extra2, p_bn2s, p_bn2t);

    // ---- classifier + log_softmax ----
    cls_lsm_kernel<<<(NNODES * 32 + 255) / 256, 256>>>(b_cls, out);
    int tail = out_size - NNODES * NCLS;
    if (tail > 0)
        tail_kernel<<<(tail + 255) / 256, 256>>>(out, NNODES * NCLS, out_size);
}

// round 5
// speedup vs baseline: 5.4098x; 1.0728x over previous
#include <cuda_runtime.h>
#include <cuda_bf16.h>
#include <cstdint>

#define NNODES 50000
#define EDGES 800000
#define FIN 256
#define HID 256
#define NCAT 1024
#define NCLS 40
#define BN_EPS 1e-5f
#define NTOT (4 * NNODES)
#define ETOT (4 * EDGES)

// ---------------- scratch (static device globals) ---------------------------
__device__ float g_T1[(size_t)NNODES * NCAT];     // x @ Wcat; slice3 later holds T2
__device__ float g_AGG[(size_t)NNODES * NCAT];    // aggregation output -> FINAL
__device__ int   g_cnt[NTOT];
__device__ float g_dinv[NTOT];
__device__ float g_invdeg[NTOT];
__device__ int   g_start[NTOT + 1];
__device__ int   g_cursor[NTOT];
__device__ int   g_bsum[1024];
__device__ int   g_esrc[ETOT];
__device__ float g_ew[ETOT];
__device__ float g_Wt[NCLS * NCAT];
__device__ float g_mask[4];
__device__ float g_bn1s[HID], g_bn1t[HID], g_bn2s[HID], g_bn2t[HID];
// bf16 split operands
__device__ __nv_bfloat16 g_xhi[(size_t)NNODES * FIN];
__device__ __nv_bfloat16 g_xlo[(size_t)NNODES * FIN];
__device__ __nv_bfloat16 g_Whi[FIN * NCAT];
__device__ __nv_bfloat16 g_Wlo[FIN * NCAT];
__device__ __nv_bfloat16 g_W2hi[HID * HID];
__device__ __nv_bfloat16 g_W2lo[HID * HID];
__device__ __nv_bfloat16 g_e1hi[(size_t)NNODES * HID];
__device__ __nv_bfloat16 g_e1lo[(size_t)NNODES * HID];

// ---------------- tiny prep kernels -----------------------------------------
__global__ void mask_kernel(const float* __restrict__ att) {
    if (threadIdx.x == 0) {
        float m = att[0];
        for (int i = 1; i < 4; i++) m = fmaxf(m, att[i]);
        float s = 0.f, e[4];
        for (int i = 0; i < 4; i++) { e[i] = expf(att[i] - m); s += e[i]; }
        for (int i = 0; i < 4; i++) g_mask[i] = e[i] / s;
    }
}

__global__ void bnfold_kernel(const float* g1, const float* b1, const float* m1, const float* v1,
                              const float* g2, const float* b2, const float* m2, const float* v2) {
    int i = blockIdx.x * blockDim.x + threadIdx.x;
    if (i >= HID) return;
    float s1 = g1[i] * rsqrtf(v1[i] + BN_EPS);
    g_bn1s[i] = s1; g_bn1t[i] = b1[i] - m1[i] * s1;
    float s2 = g2[i] * rsqrtf(v2[i] + BN_EPS);
    g_bn2s[i] = s2; g_bn2t[i] = b2[i] - m2[i] * s2;
}

__global__ void zero_cnt_kernel() {
    int i = blockIdx.x * blockDim.x + threadIdx.x;
    if (i < NTOT) g_cnt[i] = 0;
}

__global__ void count_deg_kernel(const int* __restrict__ adj) {
    int i = blockIdx.x * blockDim.x + threadIdx.x;
    if (i >= ETOT) return;
    int j = i / EDGES;
    int e = i - j * EDGES;
    int dst = adj[(size_t)j * 2 * EDGES + EDGES + e];
    atomicAdd(&g_cnt[j * NNODES + dst], 1);
}

__global__ void finalize_deg_kernel() {
    int i = blockIdx.x * blockDim.x + threadIdx.x;
    if (i >= NTOT) return;
    float d = (float)g_cnt[i] + 1.0f;
    g_dinv[i]   = rsqrtf(d);
    g_invdeg[i] = 1.0f / d;
}

__global__ void scanA_kernel() {
    __shared__ int sh[256];
    int i = blockIdx.x * 256 + threadIdx.x;
    int v = (i < NTOT) ? g_cnt[i] : 0;
    sh[threadIdx.x] = v;
    __syncthreads();
    for (int o = 1; o < 256; o <<= 1) {
        int t = (threadIdx.x >= o) ? sh[threadIdx.x - o] : 0;
        __syncthreads();
        sh[threadIdx.x] += t;
        __syncthreads();
    }
    if (i < NTOT) g_start[i] = sh[threadIdx.x] - v;
    if (threadIdx.x == 255) g_bsum[blockIdx.x] = sh[255];
}

__global__ void scanB_kernel(int nb) {
    __shared__ int sh[1024];
    int i = threadIdx.x;
    int v = (i < nb) ? g_bsum[i] : 0;
    sh[i] = v;
    __syncthreads();
    for (int o = 1; o < 1024; o <<= 1) {
        int t = (i >= o) ? sh[i - o] : 0;
        __syncthreads();
        sh[i] += t;
        __syncthreads();
    }
    g_bsum[i] = sh[i] - v;
}

__global__ void scanC_kernel() {
    int i = blockIdx.x * 256 + threadIdx.x;
    if (i < NTOT) {
        int s = g_start[i] + g_bsum[blockIdx.x];
        g_start[i] = s;
        g_cursor[i] = s;
    }
    if (i == 0) g_start[NTOT] = ETOT;
}

__global__ void scatter_kernel(const int* __restrict__ adj) {
    int i = blockIdx.x * blockDim.x + threadIdx.x;
    if (i >= ETOT) return;
    int j = i / EDGES;
    int e = i - j * EDGES;
    int src = adj[(size_t)j * 2 * EDGES + e];
    int dst = adj[(size_t)j * 2 * EDGES + EDGES + e];
    int pos = atomicAdd(&g_cursor[j * NNODES + dst], 1);
    g_esrc[pos] = src;
    g_ew[pos] = g_dinv[j * NNODES + src] * g_dinv[j * NNODES + dst];
}

// pack Wcat (fp32 concat of W_convs + W_extra) directly into bf16 hi/lo
__global__ void pack_wsplit_kernel(const float* __restrict__ W_convs,
                                   const float* __restrict__ W_extra) {
    int i = blockIdx.x * blockDim.x + threadIdx.x;
    if (i >= FIN * NCAT) return;
    int k = i / NCAT;
    int c = i - k * NCAT;
    float v;
    if (c < 3 * HID) {
        int br = c / HID, h = c - br * HID;
        v = W_convs[(size_t)br * FIN * HID + (size_t)k * HID + h];
    } else {
        v = W_extra[(size_t)k * HID + (c - 3 * HID)];
    }
    __nv_bfloat16 h16 = __float2bfloat16(v);
    g_Whi[i] = h16;
    g_Wlo[i] = __float2bfloat16(v - __bfloat162float(h16));
}

__global__ void split_dense_kernel(const float* __restrict__ src,
                                   __nv_bfloat16* __restrict__ hi,
                                   __nv_bfloat16* __restrict__ lo, int n) {
    int i = blockIdx.x * blockDim.x + threadIdx.x;
    if (i >= n) return;
    float v = src[i];
    __nv_bfloat16 h16 = __float2bfloat16(v);
    hi[i] = h16;
    lo[i] = __float2bfloat16(v - __bfloat162float(h16));
}

// e1 lives in g_AGG slice3 (row stride NCAT); emit dense [N][256] hi/lo
__global__ void split_e1_kernel() {
    int i = blockIdx.x * blockDim.x + threadIdx.x;
    if (i >= NNODES * HID) return;
    int n = i >> 8;
    int c = i & 255;
    float v = g_AGG[(size_t)n * NCAT + 3 * HID + c];
    __nv_bfloat16 h16 = __float2bfloat16(v);
    g_e1hi[i] = h16;
    g_e1lo[i] = __float2bfloat16(v - __bfloat162float(h16));
}

__global__ void transpose_wcls_kernel(const float* __restrict__ W_cls) {
    int i = blockIdx.x * blockDim.x + threadIdx.x;
    if (i >= NCLS * NCAT) return;
    int c = i / NCAT;
    int k = i - c * NCAT;
    g_Wt[i] = W_cls[(size_t)k * NCLS + c];
}

// ---------------- bf16 tensor-core GEMM (3-term split, cp.async 2-stage) -----
__device__ __forceinline__ uint32_t smem_u32(const void* p) {
    return (uint32_t)__cvta_generic_to_shared(p);
}
__device__ __forceinline__ void ldsm_x4(uint32_t* r, uint32_t addr) {
    asm volatile("ldmatrix.sync.aligned.m8n8.x4.shared.b16 {%0,%1,%2,%3},[%4];"
                 : "=r"(r[0]), "=r"(r[1]), "=r"(r[2]), "=r"(r[3]) : "r"(addr));
}
__device__ __forceinline__ void ldsm_x4_t(uint32_t* r, uint32_t addr) {
    asm volatile("ldmatrix.sync.aligned.m8n8.x4.trans.shared.b16 {%0,%1,%2,%3},[%4];"
                 : "=r"(r[0]), "=r"(r[1]), "=r"(r[2]), "=r"(r[3]) : "r"(addr));
}
__device__ __forceinline__ void mma16816(float* c, const uint32_t* a, const uint32_t* b) {
    asm volatile(
        "mma.sync.aligned.m16n8k16.row.col.f32.bf16.bf16.f32 "
        "{%0,%1,%2,%3},{%4,%5,%6,%7},{%8,%9},{%0,%1,%2,%3};"
        : "+f"(c[0]), "+f"(c[1]), "+f"(c[2]), "+f"(c[3])
        : "r"(a[0]), "r"(a[1]), "r"(a[2]), "r"(a[3]), "r"(b[0]), "r"(b[1]));
}
__device__ __forceinline__ void cp16(uint32_t dst, const void* src, bool valid) {
    int sz = valid ? 16 : 0;
    asm volatile("cp.async.cg.shared.global [%0],[%1],16,%2;"
                 :: "r"(dst), "l"(src), "r"(sz));
}

#define AS_STRIDE 40       // 32 + 8 pad (bf16 elems)
#define BS_STRIDE 136
#define KSTAGES 24         // 3 segments * 256 / 32

__global__ __launch_bounds__(256, 2) void gemm_bf16_db_kernel(
    const __nv_bfloat16* __restrict__ Ahi, const __nv_bfloat16* __restrict__ Alo,
    const __nv_bfloat16* __restrict__ Bhi, const __nv_bfloat16* __restrict__ Blo,
    int ldb, float* __restrict__ C, int ldc, int M) {
    __shared__ __nv_bfloat16 As[2][128][AS_STRIDE];
    __shared__ __nv_bfloat16 Bs[2][32][BS_STRIDE];
    int tid = threadIdx.x, lane = tid & 31, wid = tid >> 5;
    int wm = wid & 3, wn = wid >> 2;                 // warp tile 32(M) x 64(N)
    int bm = blockIdx.y * 128, bn = blockIdx.x * 128;

    // cp.async mappings
    int ar = tid >> 2, ac = (tid & 3) * 8;           // A: rows ar, 64+ar; 8-elem chunk
    int br = tid >> 4, bc = (tid & 15) * 8;          // B: rows br, 16+br

    int r0 = bm + ar, r1 = bm + 64 + ar;
    bool v0 = r0 < M, v1 = r1 < M;
    int r0c = v0 ? r0 : 0, r1c = v1 ? r1 : 0;        // clamped safe addresses

    float c[2][8][4];
#pragma unroll
    for (int t = 0; t < 2; t++)
#pragma unroll
        for (int j = 0; j < 8; j++)
#pragma unroll
            for (int q = 0; q < 4; q++) c[t][j][q] = 0.f;

    uint32_t sA0[2], sA1[2], sB0[2], sB1[2];
#pragma unroll
    for (int b = 0; b < 2; b++) {
        sA0[b] = smem_u32(&As[b][ar][ac]);
        sA1[b] = smem_u32(&As[b][64 + ar][ac]);
        sB0[b] = smem_u32(&Bs[b][br][bc]);
        sB1[b] = smem_u32(&Bs[b][16 + br][bc]);
    }

#define ISSUE(stage, buf)                                                     \
    {                                                                         \
        int k0 = (stage) * 32, seg = k0 >> 8, kk = k0 & 255;                  \
        const __nv_bfloat16* Aseg = (seg < 2) ? Ahi : Alo;                    \
        const __nv_bfloat16* Bseg = (seg == 1) ? Blo : Bhi;                   \
        cp16(sA0[buf], Aseg + (size_t)r0c * FIN + kk + ac, v0);               \
        cp16(sA1[buf], Aseg + (size_t)r1c * FIN + kk + ac, v1);               \
        cp16(sB0[buf], Bseg + (size_t)(kk + br) * ldb + bn + bc, true);       \
        cp16(sB1[buf], Bseg + (size_t)(kk + 16 + br) * ldb + bn + bc, true);  \
        asm volatile("cp.async.commit_group;");                               \
    }

    // ldmatrix base addresses (per buffer)
    uint32_t aBase[2], bBase[2];
#pragma unroll
    for (int b = 0; b < 2; b++) {
        aBase[b] = smem_u32(&As[b][wm * 32 + (lane & 15)][(lane >> 4) * 8]);
        int bRow = (lane & 7) + ((lane >> 3) & 1) * 8;
        bBase[b] = smem_u32(&Bs[b][bRow][wn * 64 + (lane >> 4) * 8]);
    }

    ISSUE(0, 0);
    for (int s = 0; s < KSTAGES; s++) {
        int buf = s & 1;
        if (s + 1 < KSTAGES) {
            ISSUE(s + 1, buf ^ 1);
            asm volatile("cp.async.wait_group 1;");
        } else {
            asm volatile("cp.async.wait_group 0;");
        }
        __syncthreads();
#pragma unroll
        for (int ks = 0; ks < 2; ks++) {           // two k16 sub-chunks
            uint32_t a[2][4];
            uint32_t aAddr = aBase[buf] + ks * 16 * 2;          // +16 bf16 cols
            ldsm_x4(a[0], aAddr);
            ldsm_x4(a[1], aAddr + 16 * AS_STRIDE * 2);          // +16 rows
            uint32_t bf[4][4];
            uint32_t bAddr = bBase[buf] + ks * 16 * BS_STRIDE * 2;  // +16 k rows
#pragma unroll
            for (int j4 = 0; j4 < 4; j4++)
                ldsm_x4_t(bf[j4], bAddr + j4 * 16 * 2);         // +16 n cols
#pragma unroll
            for (int t = 0; t < 2; t++)
#pragma unroll
                for (int j = 0; j < 8; j++)
                    mma16816(c[t][j], a[t], &bf[j >> 1][(j & 1) * 2]);
        }
        __syncthreads();
    }

    // store C
    int r = lane >> 2, cc = (lane & 3) * 2;
#pragma unroll
    for (int t = 0; t < 2; t++) {
        int m0 = bm + wm * 32 + t * 16;
#pragma unroll
        for (int j = 0; j < 8; j++) {
            int n0 = bn + wn * 64 + j * 8;
            if (m0 + r < M)
                *(float2*)(C + (size_t)(m0 + r) * ldc + n0 + cc) =
                    make_float2(c[t][j][0], c[t][j][1]);
            if (m0 + r + 8 < M)
                *(float2*)(C + (size_t)(m0 + r + 8) * ldc + n0 + cc) =
                    make_float2(c[t][j][2], c[t][j][3]);
        }
    }
#undef ISSUE
}

// ---------------- CSR gather aggregation + fused epilogue -------------------
__global__ __launch_bounds__(256) void agg_fused2_kernel(
    const int* __restrict__ start,
    const float* __restrict__ invdeg,
    const float* __restrict__ Hsrc, int ldH,
    float* __restrict__ Out, int ldO,
    int mode, int midx,
    const float* __restrict__ bias,
    const float* __restrict__ bns, const float* __restrict__ bnt) {
    float maskv = (midx >= 0) ? g_mask[midx] : 1.0f;
    int warp = (blockIdx.x * blockDim.x + threadIdx.x) >> 5;
    int lane = threadIdx.x & 31;
    if (warp >= NNODES) return;
    int n = warp;
    int h = lane * 8;

    const float4* sp = (const float4*)(Hsrc + (size_t)n * ldH + h);
    float idg = invdeg[n];
    float4 s0 = sp[0], s1 = sp[1];
    float4 a0 = make_float4(s0.x * idg, s0.y * idg, s0.z * idg, s0.w * idg);
    float4 a1 = make_float4(s1.x * idg, s1.y * idg, s1.z * idg, s1.w * idg);

    int e = start[n], eend = start[n + 1];
    for (; e + 2 <= eend; e += 2) {
        int sA = g_esrc[e], sB = g_esrc[e + 1];
        float wA = g_ew[e], wB = g_ew[e + 1];
        const float4* hA = (const float4*)(Hsrc + (size_t)sA * ldH + h);
        const float4* hB = (const float4*)(Hsrc + (size_t)sB * ldH + h);
        float4 vA0 = hA[0], vA1 = hA[1];
        float4 vB0 = hB[0], vB1 = hB[1];
        a0.x += wA * vA0.x + wB * vB0.x;
        a0.y += wA * vA0.y + wB * vB0.y;
        a0.z += wA * vA0.z + wB * vB0.z;
        a0.w += wA * vA0.w + wB * vB0.w;
        a1.x += wA * vA1.x + wB * vB1.x;
        a1.y += wA * vA1.y + wB * vB1.y;
        a1.z += wA * vA1.z + wB * vB1.z;
        a1.w += wA * vA1.w + wB * vB1.w;
    }
    if (e < eend) {
        int sA = g_esrc[e];
        float wA = g_ew[e];
        const float4* hA = (const float4*)(Hsrc + (size_t)sA * ldH + h);
        float4 vA0 = hA[0], vA1 = hA[1];
        a0.x += wA * vA0.x; a0.y += wA * vA0.y; a0.z += wA * vA0.z; a0.w += wA * vA0.w;
        a1.x += wA * vA1.x; a1.y += wA * vA1.y; a1.z += wA * vA1.z; a1.w += wA * vA1.w;
    }

    float4 b0 = *(const float4*)(bias + h);
    float4 b1 = *(const float4*)(bias + h + 4);
    a0.x += b0.x; a0.y += b0.y; a0.z += b0.z; a0.w += b0.w;
    a1.x += b1.x; a1.y += b1.y; a1.z += b1.z; a1.w += b1.w;
    if (mode != 0) {
        float4 sc0 = *(const float4*)(bns + h);
        float4 sc1 = *(const float4*)(bns + h + 4);
        float4 t0 = *(const float4*)(bnt + h);
        float4 t1 = *(const float4*)(bnt + h + 4);
        a0.x = a0.x * sc0.x + t0.x; a0.y = a0.y * sc0.y + t0.y;
        a0.z = a0.z * sc0.z + t0.z; a0.w = a0.w * sc0.w + t0.w;
        a1.x = a1.x * sc1.x + t1.x; a1.y = a1.y * sc1.y + t1.y;
        a1.z = a1.z * sc1.z + t1.z; a1.w = a1.w * sc1.w + t1.w;
    }
    a0.x = fmaxf(a0.x, 0.f) * maskv; a0.y = fmaxf(a0.y, 0.f) * maskv;
    a0.z = fmaxf(a0.z, 0.f) * maskv; a0.w = fmaxf(a0.w, 0.f) * maskv;
    a1.x = fmaxf(a1.x, 0.f) * maskv; a1.y = fmaxf(a1.y, 0.f) * maskv;
    a1.z = fmaxf(a1.z, 0.f) * maskv; a1.w = fmaxf(a1.w, 0.f) * maskv;

    float4* op = (float4*)(Out + (size_t)n * ldO + h);
    op[0] = a0;
    op[1] = a1;
}

// ---------------- fused classifier + log_softmax (warp per node) ------------
__global__ __launch_bounds__(256) void cls_lsm_kernel(const float* __restrict__ b_cls,
                                                      float* __restrict__ out) {
    __shared__ float slog[8][NCLS];
    int warp = (blockIdx.x * blockDim.x + threadIdx.x) >> 5;
    int lane = threadIdx.x & 31;
    int wl = threadIdx.x >> 5;
    if (warp >= NNODES) return;

    const float4* row = (const float4*)(g_AGG + (size_t)warp * NCAT);
    float4 r[8];
#pragma unroll
    for (int i = 0; i < 8; i++) r[i] = row[i * 32 + lane];

    for (int c = 0; c < NCLS; c++) {
        const float4* wt = (const float4*)(g_Wt + (size_t)c * NCAT);
        float acc = 0.f;
#pragma unroll
        for (int i = 0; i < 8; i++) {
            float4 q = wt[i * 32 + lane];
            acc += r[i].x * q.x + r[i].y * q.y + r[i].z * q.z + r[i].w * q.w;
        }
#pragma unroll
        for (int o = 16; o > 0; o >>= 1) acc += __shfl_xor_sync(0xffffffffu, acc, o);
        if (lane == 0) slog[wl][c] = acc + b_cls[c];
    }
    __syncwarp();
    int l2 = lane + 32;
    float v0 = (lane < NCLS) ? slog[wl][lane] : -1e30f;
    float v1 = (l2 < NCLS)   ? slog[wl][l2]   : -1e30f;
    float m = fmaxf(v0, v1);
#pragma unroll
    for (int o = 16; o > 0; o >>= 1) m = fmaxf(m, __shfl_xor_sync(0xffffffffu, m, o));
    float s = ((lane < NCLS) ? expf(v0 - m) : 0.f) + ((l2 < NCLS) ? expf(v1 - m) : 0.f);
#pragma unroll
    for (int o = 16; o > 0; o >>= 1) s += __shfl_xor_sync(0xffffffffu, s, o);
    float L = m + logf(s);
    if (lane < NCLS) out[(size_t)warp * NCLS + lane] = v0 - L;
    if (l2 < NCLS)   out[(size_t)warp * NCLS + l2]   = v1 - L;
}

__global__ void tail_kernel(float* out, int startI, int total) {
    int i = startI + blockIdx.x * blockDim.x + threadIdx.x;
    if (i < total) out[i] = 0.f;
}

// ---------------- launch ----------------------------------------------------
extern "C" void kernel_launch(void* const* d_in, const int* in_sizes, int n_in,
                              void* d_out, int out_size) {
    const float* x        = (const float*)d_in[0];
    const int*   adj      = (const int*)d_in[1];
    const float* W_convs  = (const float*)d_in[2];
    const float* b_convs  = (const float*)d_in[3];
    const float* W_extra  = (const float*)d_in[4];
    const float* b_extra  = (const float*)d_in[5];
    const float* bn1g     = (const float*)d_in[6];
    const float* bn1b     = (const float*)d_in[7];
    const float* bn1m     = (const float*)d_in[8];
    const float* bn1v     = (const float*)d_in[9];
    const float* W_extra2 = (const float*)d_in[10];
    const float* b_extra2 = (const float*)d_in[11];
    const float* bn2g     = (const float*)d_in[12];
    const float* bn2b     = (const float*)d_in[13];
    const float* bn2m     = (const float*)d_in[14];
    const float* bn2v     = (const float*)d_in[15];
    const float* att      = (const float*)d_in[16];
    const float* W_cls    = (const float*)d_in[17];
    const float* b_cls    = (const float*)d_in[18];
    float* out = (float*)d_out;

    float *p_T1, *p_AGG, *p_invdeg;
    float *p_bn1s, *p_bn1t, *p_bn2s, *p_bn2t;
    int *p_start;
    __nv_bfloat16 *p_xhi, *p_xlo, *p_Whi, *p_Wlo, *p_W2hi, *p_W2lo, *p_e1hi, *p_e1lo;
    cudaGetSymbolAddress((void**)&p_T1,    g_T1);
    cudaGetSymbolAddress((void**)&p_AGG,   g_AGG);
    cudaGetSymbolAddress((void**)&p_invdeg,g_invdeg);
    cudaGetSymbolAddress((void**)&p_start, g_start);
    cudaGetSymbolAddress((void**)&p_bn1s,  g_bn1s);
    cudaGetSymbolAddress((void**)&p_bn1t,  g_bn1t);
    cudaGetSymbolAddress((void**)&p_bn2s,  g_bn2s);
    cudaGetSymbolAddress((void**)&p_bn2t,  g_bn2t);
    cudaGetSymbolAddress((void**)&p_xhi,   g_xhi);
    cudaGetSymbolAddress((void**)&p_xlo,   g_xlo);
    cudaGetSymbolAddress((void**)&p_Whi,   g_Whi);
    cudaGetSymbolAddress((void**)&p_Wlo,   g_Wlo);
    cudaGetSymbolAddress((void**)&p_W2hi,  g_W2hi);
    cudaGetSymbolAddress((void**)&p_W2lo,  g_W2lo);
    cudaGetSymbolAddress((void**)&p_e1hi,  g_e1hi);
    cudaGetSymbolAddress((void**)&p_e1lo,  g_e1lo);

    const int SCAN_BLOCKS = (NTOT + 255) / 256;

    // ---- prep ----
    mask_kernel<<<1, 32>>>(att);
    bnfold_kernel<<<1, 256>>>(bn1g, bn1b, bn1m, bn1v, bn2g, bn2b, bn2m, bn2v);
    zero_cnt_kernel<<<SCAN_BLOCKS, 256>>>();
    count_deg_kernel<<<(ETOT + 255) / 256, 256>>>(adj);
    finalize_deg_kernel<<<SCAN_BLOCKS, 256>>>();
    scanA_kernel<<<SCAN_BLOCKS, 256>>>();
    scanB_kernel<<<1, 1024>>>(SCAN_BLOCKS);
    scanC_kernel<<<SCAN_BLOCKS, 256>>>();
    scatter_kernel<<<(ETOT + 255) / 256, 256>>>(adj);
    pack_wsplit_kernel<<<(FIN * NCAT + 255) / 256, 256>>>(W_convs, W_extra);
    split_dense_kernel<<<(NNODES * FIN + 255) / 256, 256>>>(x, p_xhi, p_xlo, NNODES * FIN);
    split_dense_kernel<<<(HID * HID + 255) / 256, 256>>>(W_extra2, p_W2hi, p_W2lo, HID * HID);
    transpose_wcls_kernel<<<(NCLS * NCAT + 255) / 256, 256>>>(W_cls);

    // ---- GEMM1 (tensor, cp.async): T1 = x @ Wcat  [50000 x 1024] ----
    {
        dim3 grid(NCAT / 128, (NNODES + 127) / 128);
        gemm_bf16_db_kernel<<<grid, 256>>>(p_xhi, p_xlo, p_Whi, p_Wlo, NCAT,
                                           p_T1, NCAT, NNODES);
    }

    // ---- aggregations (gather, fused epilogue) ----
    int agg_blocks = (NNODES * 32 + 255) / 256;
    for (int s = 0; s < 3; s++) {
        int a = s + 1;
        agg_fused2_kernel<<<agg_blocks, 256>>>(
            p_start + a * NNODES, p_invdeg + a * NNODES,
            p_T1 + s * HID, NCAT,
            p_AGG + s * HID, NCAT,
            0, s, b_convs + s * HID, nullptr, nullptr);
    }
    // extra layer 1 on adj[0]: e1 -> AGG slice3
    agg_fused2_kernel<<<agg_blocks, 256>>>(
        p_start, p_invdeg,
        p_T1 + 3 * HID, NCAT,
        p_AGG + 3 * HID, NCAT,
        1, -1, b_extra, p_bn1s, p_bn1t);
    // split e1 to bf16 hi/lo
    split_e1_kernel<<<(NNODES * HID + 255) / 256, 256>>>();
    // GEMM2 (tensor, cp.async): T2 = e1 @ W_extra2, stored into T1 slice3
    {
        dim3 grid(HID / 128, (NNODES + 127) / 128);
        gemm_bf16_db_kernel<<<grid, 256>>>(p_e1hi, p_e1lo, p_W2hi, p_W2lo, HID,
                                           p_T1 + 3 * HID, NCAT, NNODES);
    }
    // extra layer 2 on adj[0]: final extra branch into AGG slice3
    agg_fused2_kernel<<<agg_blocks, 256>>>(
        p_start, p_invdeg,
        p_T1 + 3 * HID, NCAT,
        p_AGG + 3 * HID, NCAT,
        2, 3, b_extra2, p_bn2s, p_bn2t);

    // ---- classifier + log_softmax ----
    cls_lsm_kernel<<<(NNODES * 32 + 255) / 256, 256>>>(b_cls, out);
    int tail = out_size - NNODES * NCLS;
    if (tail > 0)
        tail_kernel<<<(tail + 255) / 256, 256>>>(out, NNODES * NCLS, out_size);
}